// round 10
// baseline (speedup 1.0000x reference)
#include <cuda_runtime.h>
#include <cuda_bf16.h>

// Renderer: B=2, N=2048 points, S=128 image, K=16 per pixel, alpha composite.
//
// Single fused kernel (projection + binning + render) with an in-kernel
// global barrier:
//   Phase 1: first 64 blocks project all B*N points to NDC and scatter
//            (x, y, z, idx) into per-tile candidate lists (atomics).
//   Barrier: flag-based release; all 512 blocks are resident in wave 1
//            (64 thr / 4KB smem each), so spinning cannot deadlock.
//   Phase 2: each block = one 8x8 tile; stages its candidate list to smem,
//            each thread (one pixel) collects hits branch-light, sorts once
//            by (z, index), alpha-composites.
//   Epilogue: last block resets both barrier counters; cnt is consumed via
//            atomicExch -> all device state returns to zero each call
//            (graph-replay deterministic).
// Sort keyed on (z, index): deterministic under atomic push order and
// matches top_k's index-stable tie-breaking.

#define S_IMG    128
#define NPTS     2048
#define KHITS    16
#define HCAP     20                    // hit buffer; prune to 16 if it fills
#define RADIUS   0.02f
#define RAD2     (RADIUS * RADIUS)
#define INV_RAD2 (1.0f / RAD2)
#define ZNEAR    1.0f
#define FOCAL    1.7320508075688772f   // 1 / tan(30 deg)
#define TILE     8
#define TILES_X  (S_IMG / TILE)        // 16
#define NTILES   (TILES_X * TILES_X)   // 256 per batch
#define B_MAX    2
#define CAP      256                   // worst expected ~100 per tile

__device__ int    g_cnt [B_MAX * NTILES];           // zero at steady state
__device__ float4 g_list[B_MAX * NTILES * CAP];     // (x, y, z, idx) ~2MB
__device__ int    g_done;                           // zero at steady state
__device__ int    g_done2;                          // zero at steady state

// -------- sort nh hits ascending by (z, idx); insertion sort (nh small) ----
__device__ __forceinline__ void sort_hits(float* hz, float* hd, int* hi, int nh)
{
    for (int a = 1; a < nh; a++) {
        float z = hz[a], d = hd[a];
        int   i = hi[a];
        int k = a;
        while (k > 0 && (hz[k-1] > z || (hz[k-1] == z && hi[k-1] > i))) {
            hz[k] = hz[k-1]; hd[k] = hd[k-1]; hi[k] = hi[k-1]; k--;
        }
        hz[k] = z; hd[k] = d; hi[k] = i;
    }
}

// ------------------------------------------------------------ fused kernel --
__global__ __launch_bounds__(64) void fused_render_kernel(
    const float* __restrict__ points,   // [B, N, 3]
    const float* __restrict__ eye,      // [B, 3]
    const float* __restrict__ colors,   // [B, N, 3]
    float* __restrict__ out,            // [B, S, S, 3]
    int B)
{
    __shared__ float4 sl[CAP];
    __shared__ int s_cnt;

    const int tid = threadIdx.x;        // 0..63
    const int b   = blockIdx.z;
    const int tcx = blockIdx.x;
    const int tcy = blockIdx.y;
    const int nblocks = gridDim.x * gridDim.y * gridDim.z;
    const int bid = (blockIdx.z * gridDim.y + blockIdx.y) * gridDim.x
                    + blockIdx.x;
    const int total = B * NPTS;

    // ---------------- Phase 1: project + bin (first 64 blocks do the work) -
    for (int g = bid * 64 + tid; g < total; g += nblocks * 64) {
        const int pb = g / NPTS;
        const int pi = g - pb * NPTS;

        const float ex = eye[pb * 3 + 0];
        const float ey = eye[pb * 3 + 1];
        const float ez = eye[pb * 3 + 2];

        // camera basis (look-at origin, up = +y)
        float zn  = rsqrtf(ex * ex + ey * ey + ez * ez);
        float zax = -ex * zn, zay = -ey * zn, zaz = -ez * zn;
        float xax = zaz, xaz = -zax;                 // up x z (x.y == 0)
        float xn  = rsqrtf(xax * xax + xaz * xaz);
        xax *= xn; xaz *= xn;
        float yax = zay * xaz;
        float yay = zaz * xax - zax * xaz;
        float yaz = -zay * xax;

        const float* p = points + (size_t)g * 3;
        float dx = p[0] - ex, dy = p[1] - ey, dz = p[2] - ez;
        float cz = dx * zax + dy * zay + dz * zaz;
        if (cz <= ZNEAR) continue;

        float cx = dx * xax + dz * xaz;
        float cy = dx * yax + dy * yay + dz * yaz;
        float s  = FOCAL / cz;
        float x  = cx * s;
        float y  = cy * s;

        // pixel-space footprint (over-inclusive bounds are fine)
        float c_lo = (1.0f - x - RADIUS) * (S_IMG * 0.5f) - 0.5f;
        float c_hi = (1.0f - x + RADIUS) * (S_IMG * 0.5f) - 0.5f;
        float r_lo = (1.0f - y - RADIUS) * (S_IMG * 0.5f) - 0.5f;
        float r_hi = (1.0f - y + RADIUS) * (S_IMG * 0.5f) - 0.5f;
        if (c_hi < 0.0f || c_lo > (float)(S_IMG - 1) ||
            r_hi < 0.0f || r_lo > (float)(S_IMG - 1)) continue;

        int cmin = max(0,         (int)floorf(c_lo));
        int cmax = min(S_IMG - 1, (int)ceilf (c_hi));
        int rmin = max(0,         (int)floorf(r_lo));
        int rmax = min(S_IMG - 1, (int)ceilf (r_hi));

        int txmin = cmin >> 3, txmax = cmax >> 3;
        int tymin = rmin >> 3, tymax = rmax >> 3;

        float4 e = make_float4(x, y, cz, __int_as_float(pi));
        for (int ty = tymin; ty <= tymax; ty++) {
            for (int tx = txmin; tx <= txmax; tx++) {
                int t = (pb * NTILES) + ty * TILES_X + tx;
                int slot = atomicAdd(&g_cnt[t], 1);
                if (slot < CAP) g_list[(size_t)t * CAP + slot] = e;
            }
        }
    }

    // ---------------- Global barrier (all blocks resident => no deadlock) --
    __threadfence();
    __syncthreads();
    const int t = (b * NTILES) + tcy * TILES_X + tcx;
    if (tid == 0) {
        atomicAdd(&g_done, 1);
        volatile int* dp = &g_done;
        while (*dp < nblocks) __nanosleep(64);
        __threadfence();
        s_cnt = atomicExch(&g_cnt[t], 0);   // read + reset in one op
    }
    __syncthreads();
    const int cnt = min(s_cnt, CAP);

    // ---------------- Phase 2: render this tile ----------------------------
    const int col = tcx * TILE + (tid & (TILE - 1));
    const int row = tcy * TILE + (tid >> 3);
    float* o = out + (size_t)((b * S_IMG + row) * S_IMG + col) * 3;

    if (cnt == 0) {
        o[0] = 0.0f; o[1] = 0.0f; o[2] = 0.0f;
    } else {
        // stage candidate list into shared memory (parallel loads)
        const float4* __restrict__ list = g_list + (size_t)t * CAP;
        for (int j = tid; j < cnt; j += 64) sl[j] = list[j];
        __syncthreads();

        const float inv = 1.0f / (float)S_IMG;
        const float pxc = 1.0f - (2.0f * col + 1.0f) * inv;
        const float pyc = 1.0f - (2.0f * row + 1.0f) * inv;

        // hit collection: no sorting in the hot loop
        float hz[HCAP];
        float hd[HCAP];
        int   hi[HCAP];
        int   nh = 0;

        for (int j = 0; j < cnt; j++) {
            float4 q = sl[j];
            float ddx = pxc - q.x;
            float ddy = pyc - q.y;
            float d2  = fmaf(ddx, ddx, ddy * ddy);
            if (d2 < RAD2) {
                hz[nh] = q.z; hd[nh] = d2; hi[nh] = __float_as_int(q.w);
                nh++;
                if (nh == HCAP) {            // extremely rare: prune to 16
                    sort_hits(hz, hd, hi, nh);
                    nh = KHITS;
                }
            }
        }

        sort_hits(hz, hd, hi, nh);
        const int nk = min(nh, KHITS);

        // front-to-back alpha compositing
        float T = 1.0f, r = 0.0f, g = 0.0f, bl = 0.0f;
        for (int k = 0; k < nk; k++) {
            float a = 1.0f - hd[k] * INV_RAD2;
            a = fminf(fmaxf(a, 0.0f), 1.0f);
            const float* c = colors + (size_t)(b * NPTS + hi[k]) * 3;
            float w = a * T;
            r  += w * c[0];
            g  += w * c[1];
            bl += w * c[2];
            T *= (1.0f - a);
        }

        o[0] = r; o[1] = g; o[2] = bl;
    }

    // ---------------- Epilogue: last block restores zero state -------------
    if (tid == 0) {
        int old = atomicAdd(&g_done2, 1);
        if (old == nblocks - 1) {
            g_done  = 0;
            g_done2 = 0;
            __threadfence();
        }
    }
}

// ----------------------------------------------------------------- launch ---
extern "C" void kernel_launch(void* const* d_in, const int* in_sizes, int n_in,
                              void* d_out, int out_size) {
    const float* points = (const float*)d_in[0];
    const float* eye    = (const float*)d_in[1];
    const float* colors = (const float*)d_in[2];
    float* out          = (float*)d_out;

    const int B = in_sizes[1] / 3;     // eye is [B,3]

    dim3 grid(TILES_X, TILES_X, B);
    fused_render_kernel<<<grid, 64>>>(points, eye, colors, out, B);
}

// round 11
// speedup vs baseline: 1.1669x; 1.1669x over previous
#include <cuda_runtime.h>
#include <cuda_bf16.h>

// Renderer: B=2, N=2048 points, S=128 image, K=16 per pixel, alpha composite.
//
// Scatter-binning + smem staging + ORDER-INDEPENDENT compositing:
//   K1 (project+bin): project each point to NDC; if visible, push
//       (x, y, z, idx) into the per-tile candidate list of every 8x8-pixel
//       tile its radius-R footprint overlaps.
//   K2 (render): one 64-thread block per tile. Block stages its candidate
//       list into shared memory (sentinel-padded to a multiple of 4), each
//       thread (one pixel) collects hits branch-light, then composites
//       WITHOUT sorting: w_j = a_j * prod_{(z_i,i)<(z_j,j)} (1-a_i), an
//       O(nh^2) set function over packed (z,idx) keys. Rare nh>16 overflow
//       falls back to sort-and-truncate (exact streaming top-16).
// Keys (z_bits<<32)|idx preserve (z, index) lexicographic order ->
// deterministic under atomic push order, matches top_k tie-breaking.

#define S_IMG    128
#define NPTS     2048
#define KHITS    16
#define HCAP     20                    // hit buffer; prune to 16 if it fills
#define RADIUS   0.02f
#define RAD2     (RADIUS * RADIUS)
#define INV_RAD2 (1.0f / RAD2)
#define ZNEAR    1.0f
#define FOCAL    1.7320508075688772f   // 1 / tan(30 deg)
#define TILE     8
#define TILES_X  (S_IMG / TILE)        // 16
#define NTILES   (TILES_X * TILES_X)   // 256 per batch
#define B_MAX    2
#define CAP      256                   // worst expected ~100 per tile

__device__ int    g_cnt [B_MAX * NTILES];           // zero at steady state
__device__ float4 g_list[B_MAX * NTILES * CAP];     // (x, y, z, idx) ~2MB

// ------------------------------------------------------------ project+bin --
__global__ __launch_bounds__(256) void project_bin_kernel(
    const float* __restrict__ points,   // [B, N, 3]
    const float* __restrict__ eye)      // [B, 3]
{
    const int g = blockIdx.x * blockDim.x + threadIdx.x;
    const int b = g / NPTS;
    const int i = g - b * NPTS;

    const float ex = eye[b * 3 + 0];
    const float ey = eye[b * 3 + 1];
    const float ez = eye[b * 3 + 2];

    // camera basis (look-at origin, up = +y)
    float zn  = rsqrtf(ex * ex + ey * ey + ez * ez);
    float zax = -ex * zn, zay = -ey * zn, zaz = -ez * zn;
    float xax = zaz, xaz = -zax;                 // up x z (x.y == 0)
    float xn  = rsqrtf(xax * xax + xaz * xaz);
    xax *= xn; xaz *= xn;
    float yax = zay * xaz;
    float yay = zaz * xax - zax * xaz;
    float yaz = -zay * xax;

    const float* p = points + (size_t)g * 3;
    float dx = p[0] - ex, dy = p[1] - ey, dz = p[2] - ez;
    float cz = dx * zax + dy * zay + dz * zaz;
    if (cz <= ZNEAR) return;

    float cx = dx * xax + dz * xaz;
    float cy = dx * yax + dy * yay + dz * yaz;
    float s  = FOCAL / cz;
    float x  = cx * s;
    float y  = cy * s;

    // pixel-space footprint (over-inclusive bounds are fine)
    float c_lo = (1.0f - x - RADIUS) * (S_IMG * 0.5f) - 0.5f;
    float c_hi = (1.0f - x + RADIUS) * (S_IMG * 0.5f) - 0.5f;
    float r_lo = (1.0f - y - RADIUS) * (S_IMG * 0.5f) - 0.5f;
    float r_hi = (1.0f - y + RADIUS) * (S_IMG * 0.5f) - 0.5f;
    if (c_hi < 0.0f || c_lo > (float)(S_IMG - 1) ||
        r_hi < 0.0f || r_lo > (float)(S_IMG - 1)) return;

    int cmin = max(0,         (int)floorf(c_lo));
    int cmax = min(S_IMG - 1, (int)ceilf (c_hi));
    int rmin = max(0,         (int)floorf(r_lo));
    int rmax = min(S_IMG - 1, (int)ceilf (r_hi));

    int txmin = cmin >> 3, txmax = cmax >> 3;
    int tymin = rmin >> 3, tymax = rmax >> 3;

    float4 e = make_float4(x, y, cz, __int_as_float(i));
    for (int ty = tymin; ty <= tymax; ty++) {
        for (int tx = txmin; tx <= txmax; tx++) {
            int t = (b * NTILES) + ty * TILES_X + tx;
            int slot = atomicAdd(&g_cnt[t], 1);
            if (slot < CAP) g_list[(size_t)t * CAP + slot] = e;
        }
    }
}

// -------- rare path: sort nh hits ascending by key; insertion sort ---------
__device__ __forceinline__ void sort_hits(unsigned long long* hk, float* hd,
                                          int nh)
{
    for (int a = 1; a < nh; a++) {
        unsigned long long k = hk[a];
        float d = hd[a];
        int j = a;
        while (j > 0 && hk[j-1] > k) {
            hk[j] = hk[j-1]; hd[j] = hd[j-1]; j--;
        }
        hk[j] = k; hd[j] = d;
    }
}

// ----------------------------------------------------------------- render --
__global__ __launch_bounds__(64) void render_tiled_kernel(
    const float* __restrict__ colors,   // [B, N, 3]
    float* __restrict__ out)            // [B, S, S, 3]
{
    __shared__ float4 sl[CAP + 4];

    const int b   = blockIdx.z;
    const int tcx = blockIdx.x;
    const int tcy = blockIdx.y;
    const int tid = threadIdx.x;        // 0..63

    const int t   = (b * NTILES) + tcy * TILES_X + tcx;
    const int cnt = min(g_cnt[t], CAP);

    // this thread's pixel
    const int col = tcx * TILE + (tid & (TILE - 1));
    const int row = tcy * TILE + (tid >> 3);
    float* o = out + (size_t)((b * S_IMG + row) * S_IMG + col) * 3;

    if (cnt == 0) {                      // fast path: majority of tiles
        if (tid == 0) g_cnt[t] = 0;
        o[0] = 0.0f; o[1] = 0.0f; o[2] = 0.0f;
        return;
    }

    // stage candidate list into smem; pad to multiple of 4 with sentinels
    const int cnt4 = (cnt + 3) & ~3;
    const float4* __restrict__ list = g_list + (size_t)t * CAP;
    for (int j = tid; j < cnt4; j += 64)
        sl[j] = (j < cnt) ? __ldg(&list[j])
                          : make_float4(1e30f, 1e30f, 1e30f, 0.0f);
    __syncthreads();
    if (tid == 0) g_cnt[t] = 0;         // restore zero state for next call

    const float inv = 1.0f / (float)S_IMG;
    const float pxc = 1.0f - (2.0f * col + 1.0f) * inv;
    const float pyc = 1.0f - (2.0f * row + 1.0f) * inv;

    // ---- hit collection (no sorting in the hot loop) ----
    // key = (z_bits << 32) | idx : ascending key == ascending (z, idx)
    unsigned long long hk[HCAP];
    float hd[HCAP];
    int   nh = 0;

    #pragma unroll 4
    for (int j = 0; j < cnt4; j++) {
        float4 q = sl[j];
        float ddx = pxc - q.x;
        float ddy = pyc - q.y;
        float d2  = fmaf(ddx, ddx, ddy * ddy);
        if (d2 < RAD2) {
            hk[nh] = ((unsigned long long)__float_as_uint(q.z) << 32)
                     | (unsigned int)__float_as_int(q.w);
            hd[nh] = d2;
            nh++;
            if (nh == HCAP) {            // extremely rare: prune to 16 best
                sort_hits(hk, hd, nh);
                nh = KHITS;
            }
        }
    }
    if (nh > KHITS) {                    // rare: restrict to top-16 by key
        sort_hits(hk, hd, nh);
        nh = KHITS;
    }

    // ---- order-independent weights: w_j = a_j * prod_{key_i<key_j}(1-a_i)
    float r = 0.0f, g = 0.0f, bl = 0.0f;
    #pragma unroll 4
    for (int j = 0; j < nh; j++) {
        float aj = 1.0f - hd[j] * INV_RAD2;
        aj = fminf(fmaxf(aj, 0.0f), 1.0f);
        unsigned long long kj = hk[j];
        float T = 1.0f;
        for (int i = 0; i < nh; i++) {
            float ai = 1.0f - hd[i] * INV_RAD2;
            ai = fminf(fmaxf(ai, 0.0f), 1.0f);
            T = (hk[i] < kj) ? T * (1.0f - ai) : T;
        }
        float w = aj * T;
        const float* c = colors +
            (size_t)(b * NPTS + (int)(unsigned int)(kj & 0xffffffffu)) * 3;
        r  += w * __ldg(&c[0]);
        g  += w * __ldg(&c[1]);
        bl += w * __ldg(&c[2]);
    }

    o[0] = r; o[1] = g; o[2] = bl;
}

// ----------------------------------------------------------------- launch ---
extern "C" void kernel_launch(void* const* d_in, const int* in_sizes, int n_in,
                              void* d_out, int out_size) {
    const float* points = (const float*)d_in[0];
    const float* eye    = (const float*)d_in[1];
    const float* colors = (const float*)d_in[2];
    float* out          = (float*)d_out;

    const int B = in_sizes[1] / 3;     // eye is [B,3]

    project_bin_kernel<<<(B * NPTS) / 256, 256>>>(points, eye);

    dim3 grid(TILES_X, TILES_X, B);
    render_tiled_kernel<<<grid, 64>>>(colors, out);
}

// round 12
// speedup vs baseline: 1.1792x; 1.0105x over previous
#include <cuda_runtime.h>
#include <cuda_bf16.h>

// Renderer: B=2, N=2048 points, S=128 image, K=16 per pixel, alpha composite.
//
// PER-PIXEL scatter binning:
//   K1 (project+bin): project each point to NDC; push (x, y, z, idx) into the
//       candidate list of every pixel whose center is within RADIUS per-axis
//       (<= 3x3 pixels per point). Lists are stored TRANSPOSED
//       (list[slot][pixel]) so the render kernel's loads coalesce.
//   K2 (render): one thread per pixel. Reads its own candidate list
//       (peak mean ~11 entries), collects exact hits (d2 < R^2), composites
//       order-independently: w_j = a_j * prod_{(z_i,i)<(z_j,j)} (1-a_i)
//       via packed 64-bit (z,idx) keys -- no sorting. Each thread re-zeroes
//       its own counter so device state returns to zero every call
//       (graph-replay deterministic).
// Keys (z_bits<<32)|idx preserve (z, index) order -> deterministic under
// atomic push order and matches top_k's index-stable tie-breaking.

#define S_IMG    128
#define NPTS     2048
#define KHITS    16
#define HCAP     20                    // hit buffer; prune to 16 if it fills
#define RADIUS   0.02f
#define RAD2     (RADIUS * RADIUS)
#define INV_RAD2 (1.0f / RAD2)
#define ZNEAR    1.0f
#define FOCAL    1.7320508075688772f   // 1 / tan(30 deg)
#define B_MAX    2
#define NPIX     (B_MAX * S_IMG * S_IMG)   // 32768
#define CAP      40                    // peak mean ~11 candidates/pixel

__device__ int    g_cnt [NPIX];             // zero at steady state
__device__ float4 g_list[CAP * NPIX];       // transposed: [slot][pixel] ~21MB

// ------------------------------------------------------------ project+bin --
__global__ __launch_bounds__(256) void project_bin_kernel(
    const float* __restrict__ points,   // [B, N, 3]
    const float* __restrict__ eye)      // [B, 3]
{
    const int g = blockIdx.x * blockDim.x + threadIdx.x;
    const int b = g / NPTS;
    const int i = g - b * NPTS;

    const float ex = eye[b * 3 + 0];
    const float ey = eye[b * 3 + 1];
    const float ez = eye[b * 3 + 2];

    // camera basis (look-at origin, up = +y)
    float zn  = rsqrtf(ex * ex + ey * ey + ez * ez);
    float zax = -ex * zn, zay = -ey * zn, zaz = -ez * zn;
    float xax = zaz, xaz = -zax;                 // up x z (x.y == 0)
    float xn  = rsqrtf(xax * xax + xaz * xaz);
    xax *= xn; xaz *= xn;
    float yax = zay * xaz;
    float yay = zaz * xax - zax * xaz;
    float yaz = -zay * xax;

    const float* p = points + (size_t)g * 3;
    float dx = p[0] - ex, dy = p[1] - ey, dz = p[2] - ez;
    float cz = dx * zax + dy * zay + dz * zaz;
    if (cz <= ZNEAR) return;

    float cx = dx * xax + dz * xaz;
    float cy = dx * yax + dy * yay + dz * yaz;
    float s  = FOCAL / cz;
    float x  = cx * s;
    float y  = cy * s;

    // pixels whose center satisfies |pxc - x| < R per axis.
    // pxc = 1-(2c+1)/S  =>  c in ((1-x-R)*S/2-0.5 , (1-x+R)*S/2-0.5).
    // Epsilon-widened; exact d2 test in K2 makes over-inclusion harmless.
    float c_lo = (1.0f - x - RADIUS) * (S_IMG * 0.5f) - 0.5f;
    float c_hi = (1.0f - x + RADIUS) * (S_IMG * 0.5f) - 0.5f;
    float r_lo = (1.0f - y - RADIUS) * (S_IMG * 0.5f) - 0.5f;
    float r_hi = (1.0f - y + RADIUS) * (S_IMG * 0.5f) - 0.5f;

    int cmin = max(0,         (int)ceilf (c_lo - 1e-4f));
    int cmax = min(S_IMG - 1, (int)floorf(c_hi + 1e-4f));
    int rmin = max(0,         (int)ceilf (r_lo - 1e-4f));
    int rmax = min(S_IMG - 1, (int)floorf(r_hi + 1e-4f));
    if (cmin > cmax || rmin > rmax) return;

    float4 e = make_float4(x, y, cz, __int_as_float(i));
    for (int rr = rmin; rr <= rmax; rr++) {
        for (int cc = cmin; cc <= cmax; cc++) {
            int pix = (b * S_IMG + rr) * S_IMG + cc;
            int slot = atomicAdd(&g_cnt[pix], 1);
            if (slot < CAP) g_list[slot * NPIX + pix] = e;
        }
    }
}

// -------- rare path: sort nh hits ascending by key; insertion sort ---------
__device__ __forceinline__ void sort_hits(unsigned long long* hk, float* hd,
                                          int nh)
{
    for (int a = 1; a < nh; a++) {
        unsigned long long k = hk[a];
        float d = hd[a];
        int j = a;
        while (j > 0 && hk[j-1] > k) {
            hk[j] = hk[j-1]; hd[j] = hd[j-1]; j--;
        }
        hk[j] = k; hd[j] = d;
    }
}

// ----------------------------------------------------------------- render --
__global__ __launch_bounds__(256) void render_px_kernel(
    const float* __restrict__ colors,   // [B, N, 3]
    float* __restrict__ out)            // [B, S, S, 3]
{
    const int pix = blockIdx.x * blockDim.x + threadIdx.x;  // 0 .. B*S*S-1
    const int b   = pix >> 14;                              // / (S*S)
    const int cnt = min(g_cnt[pix], CAP);
    g_cnt[pix] = 0;                     // restore zero state for next call

    const float inv = 1.0f / (float)S_IMG;
    const int col = pix & (S_IMG - 1);
    const int row = (pix >> 7) & (S_IMG - 1);
    const float pxc = 1.0f - (2.0f * col + 1.0f) * inv;
    const float pyc = 1.0f - (2.0f * row + 1.0f) * inv;

    // ---- hit collection: coalesced loads (transposed list layout) ----
    unsigned long long hk[HCAP];
    float hd[HCAP];
    int   nh = 0;

    #pragma unroll 4
    for (int j = 0; j < cnt; j++) {
        float4 q = __ldg(&g_list[j * NPIX + pix]);
        float ddx = pxc - q.x;
        float ddy = pyc - q.y;
        float d2  = fmaf(ddx, ddx, ddy * ddy);
        if (d2 < RAD2) {
            hk[nh] = ((unsigned long long)__float_as_uint(q.z) << 32)
                     | (unsigned int)__float_as_int(q.w);
            hd[nh] = d2;
            nh++;
            if (nh == HCAP) {            // extremely rare: prune to 16 best
                sort_hits(hk, hd, nh);
                nh = KHITS;
            }
        }
    }
    if (nh > KHITS) {                    // rare: restrict to top-16 by key
        sort_hits(hk, hd, nh);
        nh = KHITS;
    }

    // ---- order-independent weights: w_j = a_j * prod_{key_i<key_j}(1-a_i)
    float r = 0.0f, g = 0.0f, bl = 0.0f;
    #pragma unroll 4
    for (int j = 0; j < nh; j++) {
        float aj = 1.0f - hd[j] * INV_RAD2;
        aj = fminf(fmaxf(aj, 0.0f), 1.0f);
        unsigned long long kj = hk[j];
        float T = 1.0f;
        for (int i = 0; i < nh; i++) {
            float ai = 1.0f - hd[i] * INV_RAD2;
            ai = fminf(fmaxf(ai, 0.0f), 1.0f);
            T = (hk[i] < kj) ? T * (1.0f - ai) : T;
        }
        float w = aj * T;
        const float* c = colors +
            (size_t)(b * NPTS + (int)(unsigned int)(kj & 0xffffffffu)) * 3;
        r  += w * __ldg(&c[0]);
        g  += w * __ldg(&c[1]);
        bl += w * __ldg(&c[2]);
    }

    float* o = out + (size_t)pix * 3;
    o[0] = r; o[1] = g; o[2] = bl;
}

// ----------------------------------------------------------------- launch ---
extern "C" void kernel_launch(void* const* d_in, const int* in_sizes, int n_in,
                              void* d_out, int out_size) {
    const float* points = (const float*)d_in[0];
    const float* eye    = (const float*)d_in[1];
    const float* colors = (const float*)d_in[2];
    float* out          = (float*)d_out;

    const int B = in_sizes[1] / 3;     // eye is [B,3]

    project_bin_kernel<<<(B * NPTS) / 256, 256>>>(points, eye);
    render_px_kernel<<<(B * S_IMG * S_IMG) / 256, 256>>>(colors, out);
}

// round 13
// speedup vs baseline: 1.2900x; 1.0939x over previous
#include <cuda_runtime.h>
#include <cuda_bf16.h>

// Renderer: B=2, N=2048 points, S=128 image, K=16 per pixel, alpha composite.
//
// PER-PIXEL scatter binning + REGISTER-RESIDENT streaming top-16:
//   K1 (project+bin): project each point to NDC; push (x, y, z, idx) into the
//       candidate list of every pixel whose center is within RADIUS per-axis
//       (<= 3x3 pixels per point). Lists stored TRANSPOSED (list[slot][pixel])
//       so render loads coalesce.
//   K2 (render): one thread per pixel. Maintains a 16-slot register array
//       sorted ascending by packed key (z_bits<<32 | idx), updated with a
//       fully-unrolled bubble insert (static indices -> registers, no local
//       memory). Slots start at key=MAX, d2=R2 (alpha=0). Composite is the
//       plain front-to-back recurrence over the already-sorted slots.
//       Each thread re-zeroes its own counter (device state returns to zero
//       every call -> graph-replay deterministic).
// Packed keys preserve (z, index) lexicographic order -> deterministic under
// atomic push order and matches top_k's index-stable tie-breaking.

#define S_IMG    128
#define NPTS     2048
#define KHITS    16
#define RADIUS   0.02f
#define RAD2     (RADIUS * RADIUS)
#define INV_RAD2 (1.0f / RAD2)
#define ZNEAR    1.0f
#define FOCAL    1.7320508075688772f   // 1 / tan(30 deg)
#define B_MAX    2
#define NPIX     (B_MAX * S_IMG * S_IMG)   // 32768
#define CAP      40                    // peak mean ~11 candidates/pixel
#define KEY_MAX  0xffffffffffffffffULL

__device__ int    g_cnt [NPIX];             // zero at steady state
__device__ float4 g_list[CAP * NPIX];       // transposed: [slot][pixel] ~21MB

// ------------------------------------------------------------ project+bin --
__global__ __launch_bounds__(256) void project_bin_kernel(
    const float* __restrict__ points,   // [B, N, 3]
    const float* __restrict__ eye)      // [B, 3]
{
    const int g = blockIdx.x * blockDim.x + threadIdx.x;
    const int b = g / NPTS;
    const int i = g - b * NPTS;

    const float ex = eye[b * 3 + 0];
    const float ey = eye[b * 3 + 1];
    const float ez = eye[b * 3 + 2];

    // camera basis (look-at origin, up = +y)
    float zn  = rsqrtf(ex * ex + ey * ey + ez * ez);
    float zax = -ex * zn, zay = -ey * zn, zaz = -ez * zn;
    float xax = zaz, xaz = -zax;                 // up x z (x.y == 0)
    float xn  = rsqrtf(xax * xax + xaz * xaz);
    xax *= xn; xaz *= xn;
    float yax = zay * xaz;
    float yay = zaz * xax - zax * xaz;
    float yaz = -zay * xax;

    const float* p = points + (size_t)g * 3;
    float dx = p[0] - ex, dy = p[1] - ey, dz = p[2] - ez;
    float cz = dx * zax + dy * zay + dz * zaz;
    if (cz <= ZNEAR) return;

    float cx = dx * xax + dz * xaz;
    float cy = dx * yax + dy * yay + dz * yaz;
    float s  = FOCAL / cz;
    float x  = cx * s;
    float y  = cy * s;

    // pixels whose center satisfies |pxc - x| < R per axis.
    // pxc = 1-(2c+1)/S  =>  c in ((1-x-R)*S/2-0.5 , (1-x+R)*S/2-0.5).
    // Epsilon-widened; exact d2 test in K2 makes over-inclusion harmless.
    float c_lo = (1.0f - x - RADIUS) * (S_IMG * 0.5f) - 0.5f;
    float c_hi = (1.0f - x + RADIUS) * (S_IMG * 0.5f) - 0.5f;
    float r_lo = (1.0f - y - RADIUS) * (S_IMG * 0.5f) - 0.5f;
    float r_hi = (1.0f - y + RADIUS) * (S_IMG * 0.5f) - 0.5f;

    int cmin = max(0,         (int)ceilf (c_lo - 1e-4f));
    int cmax = min(S_IMG - 1, (int)floorf(c_hi + 1e-4f));
    int rmin = max(0,         (int)ceilf (r_lo - 1e-4f));
    int rmax = min(S_IMG - 1, (int)floorf(r_hi + 1e-4f));
    if (cmin > cmax || rmin > rmax) return;

    float4 e = make_float4(x, y, cz, __int_as_float(i));
    for (int rr = rmin; rr <= rmax; rr++) {
        for (int cc = cmin; cc <= cmax; cc++) {
            int pix = (b * S_IMG + rr) * S_IMG + cc;
            int slot = atomicAdd(&g_cnt[pix], 1);
            if (slot < CAP) g_list[slot * NPIX + pix] = e;
        }
    }
}

// ----------------------------------------------------------------- render --
__global__ __launch_bounds__(256) void render_px_kernel(
    const float* __restrict__ colors,   // [B, N, 3]
    float* __restrict__ out)            // [B, S, S, 3]
{
    const int pix = blockIdx.x * blockDim.x + threadIdx.x;  // 0 .. B*S*S-1
    const int b   = pix >> 14;                              // / (S*S)
    const int cnt = min(g_cnt[pix], CAP);
    g_cnt[pix] = 0;                     // restore zero state for next call

    const float inv = 1.0f / (float)S_IMG;
    const int col = pix & (S_IMG - 1);
    const int row = (pix >> 7) & (S_IMG - 1);
    const float pxc = 1.0f - (2.0f * col + 1.0f) * inv;
    const float pyc = 1.0f - (2.0f * row + 1.0f) * inv;

    // ---- register-resident sorted top-16 (ascending by key) ----
    // invalid slot: key = KEY_MAX, d2 = RAD2 (alpha == 0)
    unsigned long long hk[KHITS];
    float hd[KHITS];
    #pragma unroll
    for (int k = 0; k < KHITS; k++) { hk[k] = KEY_MAX; hd[k] = RAD2; }

    for (int j = 0; j < cnt; j++) {
        float4 q = __ldg(&g_list[j * NPIX + pix]);
        float ddx = pxc - q.x;
        float ddy = pyc - q.y;
        float d2  = fmaf(ddx, ddx, ddy * ddy);
        if (d2 < RAD2) {
            unsigned long long nk =
                ((unsigned long long)__float_as_uint(q.z) << 32)
                | (unsigned int)__float_as_int(q.w);
            float nd = d2;
            // fully-unrolled bubble insert: keeps 16 smallest keys, sorted
            #pragma unroll
            for (int k = 0; k < KHITS; k++) {
                bool sw = nk < hk[k];
                unsigned long long tk = hk[k];
                float td = hd[k];
                hk[k] = sw ? nk : tk;  hd[k] = sw ? nd : td;
                nk    = sw ? tk : nk;  nd    = sw ? td : nd;
            }
        }
    }

    // ---- front-to-back composite over already-sorted slots ----
    float T = 1.0f, r = 0.0f, g = 0.0f, bl = 0.0f;
    #pragma unroll
    for (int k = 0; k < KHITS; k++) {
        float a = 1.0f - hd[k] * INV_RAD2;     // == 0 for invalid slots
        a = fminf(fmaxf(a, 0.0f), 1.0f);
        float w = a * T;
        if (hk[k] != KEY_MAX) {
            const float* c = colors +
                (size_t)(b * NPTS +
                         (int)(unsigned int)(hk[k] & 0xffffffffu)) * 3;
            r  += w * __ldg(&c[0]);
            g  += w * __ldg(&c[1]);
            bl += w * __ldg(&c[2]);
        }
        T *= (1.0f - a);
    }

    float* o = out + (size_t)pix * 3;
    o[0] = r; o[1] = g; o[2] = bl;
}

// ----------------------------------------------------------------- launch ---
extern "C" void kernel_launch(void* const* d_in, const int* in_sizes, int n_in,
                              void* d_out, int out_size) {
    const float* points = (const float*)d_in[0];
    const float* eye    = (const float*)d_in[1];
    const float* colors = (const float*)d_in[2];
    float* out          = (float*)d_out;

    const int B = in_sizes[1] / 3;     // eye is [B,3]

    project_bin_kernel<<<(B * NPTS) / 256, 256>>>(points, eye);
    render_px_kernel<<<(B * S_IMG * S_IMG) / 256, 256>>>(colors, out);
}

// round 14
// speedup vs baseline: 1.3094x; 1.0151x over previous
#include <cuda_runtime.h>
#include <cuda_bf16.h>

// Renderer: B=2, N=2048 points, S=128 image, K=16 per pixel, alpha composite.
//
// PER-PIXEL scatter binning + register-resident streaming top-16 + 4-wide
// batched candidate loads:
//   K1 (project+bin): project each point to NDC; push (x, y, z, idx) into the
//       candidate list of every pixel whose center is within RADIUS per-axis
//       (<= 3x3 pixels per point). Lists stored TRANSPOSED (list[slot][pixel])
//       so render loads coalesce.
//   K2 (render): one thread per pixel. Candidate loop manually unrolled 4x:
//       four independent __ldg's issue back-to-back (MLP=4) before their
//       distance tests, hiding L2 latency. Hits maintain a 16-slot register
//       array sorted ascending by packed key (z_bits<<32 | idx) via a
//       fully-unrolled bubble insert (no local memory). Composite is the
//       plain front-to-back recurrence over the already-sorted slots.
//       Each thread re-zeroes its own counter (device state returns to zero
//       every call -> graph-replay deterministic).
// Packed keys preserve (z, index) lexicographic order -> deterministic under
// atomic push order and matches top_k's index-stable tie-breaking.

#define S_IMG    128
#define NPTS     2048
#define KHITS    16
#define RADIUS   0.02f
#define RAD2     (RADIUS * RADIUS)
#define INV_RAD2 (1.0f / RAD2)
#define ZNEAR    1.0f
#define FOCAL    1.7320508075688772f   // 1 / tan(30 deg)
#define B_MAX    2
#define NPIX     (B_MAX * S_IMG * S_IMG)   // 32768
#define CAP      40                    // peak mean ~11 candidates/pixel
#define KEY_MAX  0xffffffffffffffffULL

__device__ int    g_cnt [NPIX];             // zero at steady state
__device__ float4 g_list[CAP * NPIX];       // transposed: [slot][pixel] ~21MB

// ------------------------------------------------------------ project+bin --
__global__ __launch_bounds__(256) void project_bin_kernel(
    const float* __restrict__ points,   // [B, N, 3]
    const float* __restrict__ eye)      // [B, 3]
{
    const int g = blockIdx.x * blockDim.x + threadIdx.x;
    const int b = g / NPTS;
    const int i = g - b * NPTS;

    const float ex = eye[b * 3 + 0];
    const float ey = eye[b * 3 + 1];
    const float ez = eye[b * 3 + 2];

    // camera basis (look-at origin, up = +y)
    float zn  = rsqrtf(ex * ex + ey * ey + ez * ez);
    float zax = -ex * zn, zay = -ey * zn, zaz = -ez * zn;
    float xax = zaz, xaz = -zax;                 // up x z (x.y == 0)
    float xn  = rsqrtf(xax * xax + xaz * xaz);
    xax *= xn; xaz *= xn;
    float yax = zay * xaz;
    float yay = zaz * xax - zax * xaz;
    float yaz = -zay * xax;

    const float* p = points + (size_t)g * 3;
    float dx = p[0] - ex, dy = p[1] - ey, dz = p[2] - ez;
    float cz = dx * zax + dy * zay + dz * zaz;
    if (cz <= ZNEAR) return;

    float cx = dx * xax + dz * xaz;
    float cy = dx * yax + dy * yay + dz * yaz;
    float s  = FOCAL / cz;
    float x  = cx * s;
    float y  = cy * s;

    // pixels whose center satisfies |pxc - x| < R per axis.
    // pxc = 1-(2c+1)/S  =>  c in ((1-x-R)*S/2-0.5 , (1-x+R)*S/2-0.5).
    // Epsilon-widened; exact d2 test in K2 makes over-inclusion harmless.
    float c_lo = (1.0f - x - RADIUS) * (S_IMG * 0.5f) - 0.5f;
    float c_hi = (1.0f - x + RADIUS) * (S_IMG * 0.5f) - 0.5f;
    float r_lo = (1.0f - y - RADIUS) * (S_IMG * 0.5f) - 0.5f;
    float r_hi = (1.0f - y + RADIUS) * (S_IMG * 0.5f) - 0.5f;

    int cmin = max(0,         (int)ceilf (c_lo - 1e-4f));
    int cmax = min(S_IMG - 1, (int)floorf(c_hi + 1e-4f));
    int rmin = max(0,         (int)ceilf (r_lo - 1e-4f));
    int rmax = min(S_IMG - 1, (int)floorf(r_hi + 1e-4f));
    if (cmin > cmax || rmin > rmax) return;

    float4 e = make_float4(x, y, cz, __int_as_float(i));
    for (int rr = rmin; rr <= rmax; rr++) {
        for (int cc = cmin; cc <= cmax; cc++) {
            int pix = (b * S_IMG + rr) * S_IMG + cc;
            int slot = atomicAdd(&g_cnt[pix], 1);
            if (slot < CAP) g_list[slot * NPIX + pix] = e;
        }
    }
}

// -------- distance test + register bubble-insert (fully unrolled) ----------
__device__ __forceinline__ void try_insert(
    float4 q, float pxc, float pyc,
    unsigned long long* hk, float* hd)
{
    float ddx = pxc - q.x;
    float ddy = pyc - q.y;
    float d2  = fmaf(ddx, ddx, ddy * ddy);
    if (d2 < RAD2) {
        unsigned long long nk =
            ((unsigned long long)__float_as_uint(q.z) << 32)
            | (unsigned int)__float_as_int(q.w);
        float nd = d2;
        #pragma unroll
        for (int k = 0; k < KHITS; k++) {
            bool sw = nk < hk[k];
            unsigned long long tk = hk[k];
            float td = hd[k];
            hk[k] = sw ? nk : tk;  hd[k] = sw ? nd : td;
            nk    = sw ? tk : nk;  nd    = sw ? td : nd;
        }
    }
}

// ----------------------------------------------------------------- render --
__global__ __launch_bounds__(256) void render_px_kernel(
    const float* __restrict__ colors,   // [B, N, 3]
    float* __restrict__ out)            // [B, S, S, 3]
{
    const int pix = blockIdx.x * blockDim.x + threadIdx.x;  // 0 .. B*S*S-1
    const int b   = pix >> 14;                              // / (S*S)
    const int cnt = min(g_cnt[pix], CAP);
    g_cnt[pix] = 0;                     // restore zero state for next call

    const float inv = 1.0f / (float)S_IMG;
    const int col = pix & (S_IMG - 1);
    const int row = (pix >> 7) & (S_IMG - 1);
    const float pxc = 1.0f - (2.0f * col + 1.0f) * inv;
    const float pyc = 1.0f - (2.0f * row + 1.0f) * inv;

    // register-resident sorted top-16 (ascending by key)
    // invalid slot: key = KEY_MAX, d2 = RAD2 (alpha == 0)
    unsigned long long hk[KHITS];
    float hd[KHITS];
    #pragma unroll
    for (int k = 0; k < KHITS; k++) { hk[k] = KEY_MAX; hd[k] = RAD2; }

    // ---- candidate loop: 4-wide batched loads (MLP = 4) ----
    int j = 0;
    for (; j + 4 <= cnt; j += 4) {
        float4 q0 = __ldg(&g_list[(j + 0) * NPIX + pix]);
        float4 q1 = __ldg(&g_list[(j + 1) * NPIX + pix]);
        float4 q2 = __ldg(&g_list[(j + 2) * NPIX + pix]);
        float4 q3 = __ldg(&g_list[(j + 3) * NPIX + pix]);
        try_insert(q0, pxc, pyc, hk, hd);
        try_insert(q1, pxc, pyc, hk, hd);
        try_insert(q2, pxc, pyc, hk, hd);
        try_insert(q3, pxc, pyc, hk, hd);
    }
    for (; j < cnt; j++) {
        float4 q = __ldg(&g_list[j * NPIX + pix]);
        try_insert(q, pxc, pyc, hk, hd);
    }

    // ---- front-to-back composite over already-sorted slots ----
    float T = 1.0f, r = 0.0f, g = 0.0f, bl = 0.0f;
    #pragma unroll
    for (int k = 0; k < KHITS; k++) {
        float a = 1.0f - hd[k] * INV_RAD2;     // == 0 for invalid slots
        a = fminf(fmaxf(a, 0.0f), 1.0f);
        float w = a * T;
        if (hk[k] != KEY_MAX) {
            const float* c = colors +
                (size_t)(b * NPTS +
                         (int)(unsigned int)(hk[k] & 0xffffffffu)) * 3;
            r  += w * __ldg(&c[0]);
            g  += w * __ldg(&c[1]);
            bl += w * __ldg(&c[2]);
        }
        T *= (1.0f - a);
    }

    float* o = out + (size_t)pix * 3;
    o[0] = r; o[1] = g; o[2] = bl;
}

// ----------------------------------------------------------------- launch ---
extern "C" void kernel_launch(void* const* d_in, const int* in_sizes, int n_in,
                              void* d_out, int out_size) {
    const float* points = (const float*)d_in[0];
    const float* eye    = (const float*)d_in[1];
    const float* colors = (const float*)d_in[2];
    float* out          = (float*)d_out;

    const int B = in_sizes[1] / 3;     // eye is [B,3]

    project_bin_kernel<<<(B * NPTS) / 256, 256>>>(points, eye);
    render_px_kernel<<<(B * S_IMG * S_IMG) / 256, 256>>>(colors, out);
}